// round 14
// baseline (speedup 1.0000x reference)
#include <cuda_runtime.h>
#include <cstdint>

#define NNZ   1000000
#define NROWS 500
#define MCOLS 50000
#define D     128
#define SCAN_BLOCKS 49   // ceil(50000/1024)

// ---------------- scratch (device globals; no runtime allocation) ----------
__device__ float g_colmean[MCOLS * D];
__device__ float g_rowsum [NROWS * D];
__device__ float g_rowmean[NROWS * D];
__device__ float g_G[MCOLS * D];         // 0.25 * colmean @ W_n
__device__ float g_H[NROWS * D];         // 0.25 * rowmean @ W_m
__device__ float g_C[D];                 // 0.25*(gmean@W_both + all biases)
__device__ int   g_colcnt[MCOLS];
__device__ int   g_rowcnt[NROWS];
__device__ int   g_coloff[MCOLS + 1];
__device__ int   g_rowoff[NROWS + 1];
__device__ int   g_colcur[MCOLS];
__device__ int   g_rowcur[NROWS];
__device__ int   g_colids[NNZ];
__device__ int   g_rowids[NNZ];
__device__ int   g_partial[SCAN_BLOCKS];
__device__ int   g_poff[SCAN_BLOCKS + 1];
// W_all tf32 in mma-FRAGMENT order: [ks(16)][nwi(2)][j(4)][lane(32)][w(4)]
__device__ __align__(16) unsigned g_Wfrag[16 * 2 * 4 * 32 * 4];   // 16384 words

__device__ __forceinline__ unsigned to_tf32(float f) {
    unsigned u;
    asm("cvt.rna.tf32.f32 %0, %1;" : "=r"(u) : "f"(f));
    return u;
}
__device__ __forceinline__ uint32_t smem_u32(const void* p) {
    uint32_t a;
    asm("{ .reg .u64 t; cvta.to.shared.u64 t, %1; cvt.u32.u64 %0, t; }" : "=r"(a) : "l"(p));
    return a;
}
#define CP_ASYNC16(dst, src) \
    asm volatile("cp.async.cg.shared.global [%0], [%1], 16;" :: "r"(dst), "l"(src))
#define CP_COMMIT() asm volatile("cp.async.commit_group;" ::: "memory")
#define CP_WAIT0()  asm volatile("cp.async.wait_group 0;"  ::: "memory")

// ---------------- zeroing ----------------------------------------------------
__global__ void zero_col_k() {
    int i = blockIdx.x * blockDim.x + threadIdx.x;
    if (i < MCOLS) { g_colcnt[i] = 0; g_colcur[i] = 0; }
}
__global__ void zero_row_k() {
    int i = threadIdx.x;
    if (i < NROWS) { g_rowcnt[i] = 0; g_rowcur[i] = 0; }
}

// ---------------- W_all pre-format (once): tf32 fragment order --------------
__global__ void wprep_k(const float* __restrict__ W) {
    int i = blockIdx.x * 256 + threadIdx.x;   // grid 64 -> 16384 words
    if (i >= 16384) return;
    int w    = i & 3;
    int lane = (i >> 2) & 31;
    int j    = (i >> 7) & 3;
    int nwi  = (i >> 9) & 1;
    int ks   = i >> 10;
    int q = j * 4 + w;
    int t = lane & 3, g = lane >> 2;
    int k = ks * 8 + t + (q & 1) * 4;
    int n = nwi * 64 + (q >> 1) * 8 + g;
    g_Wfrag[i] = to_tf32(W[k * 128 + n]);
}

// ---------------- histograms -------------------------------------------------
__global__ void hist_col_k(const int* __restrict__ col_idx) {
    int e = blockIdx.x * blockDim.x + threadIdx.x;
    if (e < NNZ) atomicAdd(&g_colcnt[col_idx[e]], 1);
}
__global__ void hist_row_k(const int* __restrict__ row_idx) {  // grid 148
    __shared__ int h[NROWS];
    for (int i = threadIdx.x; i < NROWS; i += blockDim.x) h[i] = 0;
    __syncthreads();
    for (int e = blockIdx.x * blockDim.x + threadIdx.x; e < NNZ;
         e += gridDim.x * blockDim.x)
        atomicAdd(&h[row_idx[e]], 1);
    __syncthreads();
    for (int i = threadIdx.x; i < NROWS; i += blockDim.x) {
        int c = h[i];
        if (c) atomicAdd(&g_rowcnt[i], c);
    }
}

// ---------------- hierarchical column scan -----------------------------------
__global__ void scan1_k() {
    __shared__ int wsum[32];
    int i = blockIdx.x * 1024 + threadIdx.x;
    int lane = threadIdx.x & 31, wid = threadIdx.x >> 5;
    int v = (i < MCOLS) ? g_colcnt[i] : 0;
    #pragma unroll
    for (int off = 16; off > 0; off >>= 1) v += __shfl_down_sync(~0u, v, off);
    if (lane == 0) wsum[wid] = v;
    __syncthreads();
    if (wid == 0) {
        int s = wsum[lane];
        #pragma unroll
        for (int off = 16; off > 0; off >>= 1) s += __shfl_down_sync(~0u, s, off);
        if (lane == 0) g_partial[blockIdx.x] = s;
    }
}

__global__ void small_scan_k(const int* __restrict__ in, int* __restrict__ out, int n) {
    __shared__ int wsum[32];
    int tid = threadIdx.x, lane = tid & 31, wid = tid >> 5;
    int v = (tid < n) ? in[tid] : 0;
    int s = v;
    #pragma unroll
    for (int off = 1; off < 32; off <<= 1) {
        int t = __shfl_up_sync(~0u, s, off);
        if (lane >= off) s += t;
    }
    if (lane == 31) wsum[wid] = s;
    __syncthreads();
    if (wid == 0) {
        int ws = wsum[lane];
        #pragma unroll
        for (int off = 1; off < 32; off <<= 1) {
            int t = __shfl_up_sync(~0u, ws, off);
            if (lane >= off) ws += t;
        }
        wsum[lane] = ws;
    }
    __syncthreads();
    int excl = s - v + (wid > 0 ? wsum[wid - 1] : 0);
    if (tid < n) out[tid] = excl;
    if (tid == n - 1) out[n] = excl + v;
}

__global__ void scan3_k() {
    __shared__ int wsum[32];
    int i = blockIdx.x * 1024 + threadIdx.x;
    int lane = threadIdx.x & 31, wid = threadIdx.x >> 5;
    int v = (i < MCOLS) ? g_colcnt[i] : 0;
    int s = v;
    #pragma unroll
    for (int off = 1; off < 32; off <<= 1) {
        int t = __shfl_up_sync(~0u, s, off);
        if (lane >= off) s += t;
    }
    if (lane == 31) wsum[wid] = s;
    __syncthreads();
    if (wid == 0) {
        int ws = wsum[lane];
        #pragma unroll
        for (int off = 1; off < 32; off <<= 1) {
            int t = __shfl_up_sync(~0u, ws, off);
            if (lane >= off) ws += t;
        }
        wsum[lane] = ws;
    }
    __syncthreads();
    int excl = s - v + (wid > 0 ? wsum[wid - 1] : 0) + g_poff[blockIdx.x];
    if (i < MCOLS) g_coloff[i] = excl;
    if (i == MCOLS - 1) g_coloff[MCOLS] = excl + v;
}

// ---------------- scatters ---------------------------------------------------
__global__ void scatter_col_k(const int* __restrict__ col_idx) {
    int e = blockIdx.x * blockDim.x + threadIdx.x;
    if (e < NNZ) {
        int c = col_idx[e];
        int p = atomicAdd(&g_colcur[c], 1);
        g_colids[g_coloff[c] + p] = e;
    }
}
__global__ void scatter_row_k(const int* __restrict__ row_idx) {  // grid 148
    __shared__ int lcnt[NROWS];
    __shared__ int lbase[NROWS];
    const int tid = threadIdx.x;
    const int chunk = (NNZ + gridDim.x - 1) / gridDim.x;
    const int lo = blockIdx.x * chunk;
    const int hi = (lo + chunk < NNZ) ? lo + chunk : NNZ;

    for (int i = tid; i < NROWS; i += blockDim.x) lcnt[i] = 0;
    __syncthreads();
    for (int e = lo + tid; e < hi; e += blockDim.x)
        atomicAdd(&lcnt[row_idx[e]], 1);
    __syncthreads();
    for (int i = tid; i < NROWS; i += blockDim.x) {
        int c = lcnt[i];
        int b = c ? atomicAdd(&g_rowcur[i], c) : 0;
        lbase[i] = g_rowoff[i] + b;
        lcnt[i] = 0;
    }
    __syncthreads();
    for (int e = lo + tid; e < hi; e += blockDim.x) {
        int r = row_idx[e];
        int slot = atomicAdd(&lcnt[r], 1);
        g_rowids[lbase[r] + slot] = e;
    }
}

// ---------------- means ------------------------------------------------------
__global__ void colmean_k(const float* __restrict__ values) {
    int warp = (blockIdx.x * blockDim.x + threadIdx.x) >> 5;
    int lane = threadIdx.x & 31;
    if (warp >= MCOLS) return;
    int beg = g_coloff[warp], end = g_coloff[warp + 1];
    float4 acc = make_float4(0.f, 0.f, 0.f, 0.f);
    int j = beg;
    for (; j + 4 <= end; j += 4) {
        int e0 = g_colids[j], e1 = g_colids[j + 1];
        int e2 = g_colids[j + 2], e3 = g_colids[j + 3];
        float4 v0 = *(const float4*)(values + (size_t)e0 * D + lane * 4);
        float4 v1 = *(const float4*)(values + (size_t)e1 * D + lane * 4);
        float4 v2 = *(const float4*)(values + (size_t)e2 * D + lane * 4);
        float4 v3 = *(const float4*)(values + (size_t)e3 * D + lane * 4);
        acc.x += (v0.x + v1.x) + (v2.x + v3.x);
        acc.y += (v0.y + v1.y) + (v2.y + v3.y);
        acc.z += (v0.z + v1.z) + (v2.z + v3.z);
        acc.w += (v0.w + v1.w) + (v2.w + v3.w);
    }
    for (; j < end; j++) {
        int e = g_colids[j];
        float4 v = *(const float4*)(values + (size_t)e * D + lane * 4);
        acc.x += v.x; acc.y += v.y; acc.z += v.z; acc.w += v.w;
    }
    int n = end - beg;
    float inv = 1.0f / (float)(n > 1 ? n : 1);
    acc.x *= inv; acc.y *= inv; acc.z *= inv; acc.w *= inv;
    *(float4*)(g_colmean + (size_t)warp * D + lane * 4) = acc;
}

__global__ void rowmean_k(const float* __restrict__ values) {
    int r = blockIdx.x;
    int lane = threadIdx.x & 31, w = threadIdx.x >> 5;  // 8 warps
    int beg = g_rowoff[r], end = g_rowoff[r + 1];
    float4 acc = make_float4(0.f, 0.f, 0.f, 0.f);
    for (int j = beg + w; j < end; j += 8) {
        int e = g_rowids[j];
        float4 v = *(const float4*)(values + (size_t)e * D + lane * 4);
        acc.x += v.x; acc.y += v.y; acc.z += v.z; acc.w += v.w;
    }
    __shared__ float4 s[8][32];
    s[w][lane] = acc;
    __syncthreads();
    if (w == 0) {
        #pragma unroll
        for (int k = 1; k < 8; k++) {
            float4 t = s[k][lane];
            acc.x += t.x; acc.y += t.y; acc.z += t.z; acc.w += t.w;
        }
        *(float4*)(g_rowsum + (size_t)r * D + lane * 4) = acc;
        int n = end - beg;
        float inv = 1.0f / (float)(n > 1 ? n : 1);
        acc.x *= inv; acc.y *= inv; acc.z *= inv; acc.w *= inv;
        *(float4*)(g_rowmean + (size_t)r * D + lane * 4) = acc;
    }
}

// ---------------- global-mean + fused constant -------------------------------
__global__ void cconst_k(const float* __restrict__ W_both,
                         const float* __restrict__ b_all, const float* __restrict__ b_n,
                         const float* __restrict__ b_m,  const float* __restrict__ b_both) {
    __shared__ float gm[D];
    int t = threadIdx.x;
    float s = 0.f;
    for (int r = 0; r < NROWS; r++) s += g_rowsum[r * D + t];
    gm[t] = s * (1.0f / (float)NNZ);
    __syncthreads();
    float acc = 0.f;
    for (int k = 0; k < D; k++) acc += gm[k] * W_both[k * D + t];
    g_C[t] = 0.25f * (acc + b_all[t] + b_n[t] + b_m[t] + b_both[t]);
}

// ---------------- mma.sync tf32 primitive ------------------------------------
__device__ __forceinline__ void mma_tf32(float* c, const unsigned* a, unsigned b0, unsigned b1) {
    asm volatile(
        "mma.sync.aligned.m16n8k8.row.col.f32.tf32.tf32.f32 "
        "{%0,%1,%2,%3}, {%4,%5,%6,%7}, {%8,%9}, {%0,%1,%2,%3};"
        : "+f"(c[0]), "+f"(c[1]), "+f"(c[2]), "+f"(c[3])
        : "r"(a[0]), "r"(a[1]), "r"(a[2]), "r"(a[3]), "r"(b0), "r"(b1));
}

// ======== small GEMMs (G, H): out = 0.25*(A@W)  (validated path) =============
#define AS_STRIDE 68
#define WS_STRIDE 132
#define SMEM_AS   0
#define SMEM_WS   (128 * AS_STRIDE * 4)
#define SMEM_TOT  (SMEM_WS + 64 * WS_STRIDE * 4)

__global__ void __launch_bounds__(256, 2)
gemm_tc(const float* __restrict__ A, const float* __restrict__ W,
        float* __restrict__ out, int M) {
    extern __shared__ char smem[];
    float* As = (float*)(smem + SMEM_AS);
    float* Ws = (float*)(smem + SMEM_WS);

    const int tid  = threadIdx.x;
    const int lane = tid & 31;
    const int wid  = tid >> 5;
    const int g    = lane >> 2;
    const int t    = lane & 3;
    const int mw   = (wid & 3) * 32;
    const int nw   = (wid >> 2) * 64;
    const int m_base = blockIdx.x * 128;

    float acc[2][8][4];
    #pragma unroll
    for (int f = 0; f < 2; f++)
        #pragma unroll
        for (int nf = 0; nf < 8; nf++)
            #pragma unroll
            for (int i = 0; i < 4; i++) acc[f][nf][i] = 0.f;

    for (int kc = 0; kc < 128; kc += 64) {
        #pragma unroll
        for (int it = 0; it < 8; it++) {
            int i = it * 256 + tid;
            int m = i >> 4, kq = i & 15;
            int row = m_base + m;
            if (row >= M) row = M - 1;
            float4 v = *(const float4*)(A + (size_t)row * 128 + kc + kq * 4);
            unsigned* dst = (unsigned*)(As + m * AS_STRIDE + kq * 4);
            dst[0] = to_tf32(v.x); dst[1] = to_tf32(v.y);
            dst[2] = to_tf32(v.z); dst[3] = to_tf32(v.w);
        }
        #pragma unroll
        for (int it = 0; it < 8; it++) {
            int i = it * 256 + tid;
            int k = i >> 5, nq = i & 31;
            float4 v = *(const float4*)(W + (size_t)(kc + k) * 128 + nq * 4);
            unsigned* dst = (unsigned*)(Ws + k * WS_STRIDE + nq * 4);
            dst[0] = to_tf32(v.x); dst[1] = to_tf32(v.y);
            dst[2] = to_tf32(v.z); dst[3] = to_tf32(v.w);
        }
        __syncthreads();

        #pragma unroll
        for (int ks = 0; ks < 8; ks++) {
            int k0 = ks * 8;
            unsigned a[2][4];
            #pragma unroll
            for (int f = 0; f < 2; f++) {
                const unsigned* ap = (const unsigned*)(As + (mw + f * 16 + g) * AS_STRIDE + k0 + t);
                const unsigned* ap8 = ap + 8 * AS_STRIDE;
                a[f][0] = ap[0];  a[f][1] = ap8[0];
                a[f][2] = ap[4];  a[f][3] = ap8[4];
            }
            #pragma unroll
            for (int nf = 0; nf < 8; nf++) {
                int n = nw + nf * 8 + g;
                unsigned b0 = *(const unsigned*)(Ws + (k0 + t) * WS_STRIDE + n);
                unsigned b1 = *(const unsigned*)(Ws + (k0 + t + 4) * WS_STRIDE + n);
                mma_tf32(acc[0][nf], a[0], b0, b1);
                mma_tf32(acc[1][nf], a[1], b0, b1);
            }
        }
        __syncthreads();
    }

    #pragma unroll
    for (int f = 0; f < 2; f++) {
        #pragma unroll
        for (int nf = 0; nf < 8; nf++) {
            int nb = nw + nf * 8 + 2 * t;
            #pragma unroll
            for (int half = 0; half < 2; half++) {
                int m_loc = mw + f * 16 + g + half * 8;
                int e = m_base + m_loc;
                if (e >= M) continue;
                float2 o;
                o.x = acc[f][nf][half * 2 + 0] * 0.25f;
                o.y = acc[f][nf][half * 2 + 1] * 0.25f;
                *(float2*)(out + (size_t)e * 128 + nb) = o;
            }
        }
    }
}

// ======== main GEMM: fragment A + RESIDENT fragment W (cp.async), fused epi ==
// out = 0.25*(A@W_all) + G[col] + H[row] + C
// AsF chunk: [ks(8)][mwi(4)][f(2)][lanepos^ks (32)][w(4)]; 32 KB
// WfFull:    all 16 ks-steps fragment order; 64 KB, loaded once via cp.async
#define MS_ASF  0                              // 32768
#define MS_WF   32768                          // 65536
#define MS_SC   98304
#define MS_IC   98816
#define MS_IR   99328
#define MS_TOT  99840

__global__ void __launch_bounds__(256, 2)
gemm_tcm(const float* __restrict__ A, float* __restrict__ out, int M,
         const int* __restrict__ colidx, const int* __restrict__ rowidx) {
    extern __shared__ char smem[];
    unsigned* AsF = (unsigned*)(smem + MS_ASF);
    uint4*    Wf  = (uint4*)(smem + MS_WF);
    float* sC = (float*)(smem + MS_SC);
    int*   sc = (int*)  (smem + MS_IC);
    int*   sr = (int*)  (smem + MS_IR);

    const int tid  = threadIdx.x;
    const int lane = tid & 31;
    const int wid  = tid >> 5;
    const int g    = lane >> 2;
    const int t    = lane & 3;
    const int mw   = (wid & 3) * 32;
    const int mwi  = (wid & 3);
    const int nw   = (wid >> 2) * 64;
    const int nwi  = (wid >> 2);
    const int m_base = blockIdx.x * 128;

    // resident W: one 64 KB cp.async copy (4096 uint4, 16/thread)
    {
        uint32_t wdst = smem_u32(Wf) + tid * 16;
        const uint4* wsrc = (const uint4*)g_Wfrag + tid;
        #pragma unroll
        for (int it = 0; it < 16; it++)
            CP_ASYNC16(wdst + it * 4096u, wsrc + it * 256);
        CP_COMMIT();
    }

    if (tid < 128) {
        int e = m_base + tid;
        if (e >= M) e = M - 1;
        sc[tid] = colidx[e];
        sr[tid] = rowidx[e];
        sC[tid] = g_C[tid];
    }

    float acc[2][8][4];
    #pragma unroll
    for (int f = 0; f < 2; f++)
        #pragma unroll
        for (int nf = 0; nf < 8; nf++)
            #pragma unroll
            for (int i = 0; i < 4; i++) acc[f][nf][i] = 0.f;

    for (int kc = 0; kc < 128; kc += 64) {
        // A chunk -> fragment-ordered smem (cvt at store, ks-XOR swizzle)
        #pragma unroll
        for (int it = 0; it < 8; it++) {
            int i = it * 256 + tid;
            int m = i >> 4, kq = i & 15;
            int row = m_base + m;
            if (row >= M) row = M - 1;
            float4 v = *(const float4*)(A + (size_t)row * 128 + kc + kq * 4);
            int ks = kq >> 1, half = kq & 1;
            int fm = (m >> 4) & 1, r8 = (m >> 3) & 1, gg = m & 7;
            unsigned* basep = AsF + ks * 1024 + (m >> 5) * 256 + fm * 128 + half * 2 + r8;
            basep[(((gg * 4 + 0) ^ ks)) << 2] = to_tf32(v.x);
            basep[(((gg * 4 + 1) ^ ks)) << 2] = to_tf32(v.y);
            basep[(((gg * 4 + 2) ^ ks)) << 2] = to_tf32(v.z);
            basep[(((gg * 4 + 3) ^ ks)) << 2] = to_tf32(v.w);
        }
        if (kc == 0) CP_WAIT0();   // W resident before first mma
        __syncthreads();

        #pragma unroll
        for (int ks = 0; ks < 8; ks++) {
            int ksg = (kc >> 3) + ks;   // global ks into resident W
            // A fragments: 2 conflict-free LDS.128 (swizzled lane)
            const uint4* ap = (const uint4*)AsF + (size_t)(ks * 256 + mwi * 64) + (lane ^ ks);
            uint4 qa0 = ap[0];       // f = 0
            uint4 qa1 = ap[32];      // f = 1
            unsigned a0[4] = {qa0.x, qa0.y, qa0.z, qa0.w};
            unsigned a1[4] = {qa1.x, qa1.y, qa1.z, qa1.w};
            // B fragments: 4 conflict-free LDS.128 -> breg[16]
            unsigned breg[16];
            {
                const uint4* bp = Wf + (size_t)((ksg * 2 + nwi) * 4) * 32 + lane;
                uint4 q0 = bp[0];
                uint4 q1 = bp[32];
                uint4 q2 = bp[64];
                uint4 q3 = bp[96];
                breg[0]=q0.x; breg[1]=q0.y; breg[2]=q0.z; breg[3]=q0.w;
                breg[4]=q1.x; breg[5]=q1.y; breg[6]=q1.z; breg[7]=q1.w;
                breg[8]=q2.x; breg[9]=q2.y; breg[10]=q2.z; breg[11]=q2.w;
                breg[12]=q3.x; breg[13]=q3.y; breg[14]=q3.z; breg[15]=q3.w;
            }
            #pragma unroll
            for (int nf = 0; nf < 8; nf++) {
                mma_tf32(acc[0][nf], a0, breg[2 * nf], breg[2 * nf + 1]);
                mma_tf32(acc[1][nf], a1, breg[2 * nf], breg[2 * nf + 1]);
            }
        }
        if (kc == 0) __syncthreads();   // AsF reuse barrier between chunks
    }

    #pragma unroll
    for (int f = 0; f < 2; f++) {
        #pragma unroll
        for (int nf = 0; nf < 8; nf++) {
            int nb = nw + nf * 8 + 2 * t;
            #pragma unroll
            for (int half = 0; half < 2; half++) {
                int m_loc = mw + f * 16 + g + half * 8;
                int e = m_base + m_loc;
                if (e >= M) continue;
                float2 o;
                o.x = acc[f][nf][half * 2 + 0] * 0.25f;
                o.y = acc[f][nf][half * 2 + 1] * 0.25f;
                int c = sc[m_loc], r = sr[m_loc];
                float2 gv = *(const float2*)(g_G + (size_t)c * 128 + nb);
                float2 hv = *(const float2*)(g_H + (size_t)r * 128 + nb);
                o.x += gv.x + hv.x + sC[nb];
                o.y += gv.y + hv.y + sC[nb + 1];
                *(float2*)(out + (size_t)e * 128 + nb) = o;
            }
        }
    }
}

// ---------------------------------------------------------------------------
extern "C" void kernel_launch(void* const* d_in, const int* in_sizes, int n_in,
                              void* d_out, int out_size) {
    const float* values  = (const float*)d_in[0];
    const int*   row_idx = (const int*)  d_in[1];
    const int*   col_idx = (const int*)  d_in[2];
    const float* W_all   = (const float*)d_in[3];
    const float* b_all   = (const float*)d_in[4];
    const float* W_n     = (const float*)d_in[5];
    const float* b_n     = (const float*)d_in[6];
    const float* W_m     = (const float*)d_in[7];
    const float* b_m     = (const float*)d_in[8];
    const float* W_both  = (const float*)d_in[9];
    const float* b_both  = (const float*)d_in[10];
    float* out = (float*)d_out;

    static cudaStream_t s_col = nullptr, s_row = nullptr;
    static cudaEvent_t ev_fork = nullptr, ev_jc = nullptr, ev_jr = nullptr;
    if (!s_col) {
        cudaStreamCreateWithFlags(&s_col, cudaStreamNonBlocking);
        cudaStreamCreateWithFlags(&s_row, cudaStreamNonBlocking);
        cudaEventCreateWithFlags(&ev_fork, cudaEventDisableTiming);
        cudaEventCreateWithFlags(&ev_jc, cudaEventDisableTiming);
        cudaEventCreateWithFlags(&ev_jr, cudaEventDisableTiming);
        cudaFuncSetAttribute(gemm_tc,  cudaFuncAttributeMaxDynamicSharedMemorySize, SMEM_TOT);
        cudaFuncSetAttribute(gemm_tcm, cudaFuncAttributeMaxDynamicSharedMemorySize, MS_TOT);
    }

    float* colmean_p; cudaGetSymbolAddress((void**)&colmean_p, g_colmean);
    float* rowmean_p; cudaGetSymbolAddress((void**)&rowmean_p, g_rowmean);
    float* G_p;       cudaGetSymbolAddress((void**)&G_p, g_G);
    float* H_p;       cudaGetSymbolAddress((void**)&H_p, g_H);
    int* partial_p;   cudaGetSymbolAddress((void**)&partial_p, g_partial);
    int* poff_p;      cudaGetSymbolAddress((void**)&poff_p, g_poff);
    int* rowcnt_p;    cudaGetSymbolAddress((void**)&rowcnt_p, g_rowcnt);
    int* rowoff_p;    cudaGetSymbolAddress((void**)&rowoff_p, g_rowoff);

    cudaEventRecord(ev_fork, 0);
    cudaStreamWaitEvent(s_col, ev_fork, 0);
    cudaStreamWaitEvent(s_row, ev_fork, 0);

    // ---- col chain (s_col) ----
    wprep_k<<<64, 256, 0, s_col>>>(W_all);
    zero_col_k<<<(MCOLS + 255) / 256, 256, 0, s_col>>>();
    hist_col_k<<<(NNZ + 255) / 256, 256, 0, s_col>>>(col_idx);
    scan1_k<<<SCAN_BLOCKS, 1024, 0, s_col>>>();
    small_scan_k<<<1, 1024, 0, s_col>>>(partial_p, poff_p, SCAN_BLOCKS);
    scan3_k<<<SCAN_BLOCKS, 1024, 0, s_col>>>();
    scatter_col_k<<<(NNZ + 255) / 256, 256, 0, s_col>>>(col_idx);
    colmean_k<<<(MCOLS * 32 + 255) / 256, 256, 0, s_col>>>(values);
    gemm_tc<<<(MCOLS + 127) / 128, 256, SMEM_TOT, s_col>>>(colmean_p, W_n, G_p, MCOLS);

    // ---- row chain (s_row) ----
    zero_row_k<<<1, 512, 0, s_row>>>();
    hist_row_k<<<148, 256, 0, s_row>>>(row_idx);
    small_scan_k<<<1, 1024, 0, s_row>>>(rowcnt_p, rowoff_p, NROWS);
    scatter_row_k<<<148, 256, 0, s_row>>>(row_idx);
    rowmean_k<<<NROWS, 256, 0, s_row>>>(values);
    cconst_k<<<1, 128, 0, s_row>>>(W_both, b_all, b_n, b_m, b_both);
    gemm_tc<<<(NROWS + 127) / 128, 256, SMEM_TOT, s_row>>>(rowmean_p, W_m, H_p, NROWS);

    // join, then main GEMM (fused epilogue)
    cudaEventRecord(ev_jc, s_col);
    cudaEventRecord(ev_jr, s_row);
    cudaStreamWaitEvent(0, ev_jc, 0);
    cudaStreamWaitEvent(0, ev_jr, 0);
    gemm_tcm<<<(NNZ + 127) / 128, 256, MS_TOT>>>(values, out, NNZ, col_idx, row_idx);
}

// round 15
// speedup vs baseline: 1.1137x; 1.1137x over previous
#include <cuda_runtime.h>
#include <cstdint>

#define NNZ   1000000
#define NROWS 500
#define MCOLS 50000
#define D     128
#define SCAN_BLOCKS 49   // ceil(50000/1024)

// ---------------- scratch (device globals; no runtime allocation) ----------
__device__ float g_colmean[MCOLS * D];
__device__ float g_rowsum [NROWS * D];
__device__ float g_rowmean[NROWS * D];
__device__ float g_G[MCOLS * D];         // 0.25 * colmean @ W_n
__device__ float g_H[NROWS * D];         // 0.25 * rowmean @ W_m
__device__ float g_C[D];                 // 0.25*(gmean@W_both + all biases)
__device__ int   g_colcnt[MCOLS];
__device__ int   g_rowcnt[NROWS];
__device__ int   g_coloff[MCOLS + 1];
__device__ int   g_rowoff[NROWS + 1];
__device__ int   g_colcur[MCOLS];
__device__ int   g_rowcur[NROWS];
__device__ int   g_colids[NNZ];
__device__ int   g_rowids[NNZ];
__device__ int   g_partial[SCAN_BLOCKS];
__device__ int   g_poff[SCAN_BLOCKS + 1];
// W_all tf32 in mma-FRAGMENT order: [ks(16)][nwi(2)][j(4)][lane(32)][w(4)]
__device__ __align__(16) unsigned g_Wfrag[16 * 2 * 4 * 32 * 4];   // 16384 words

__device__ __forceinline__ unsigned to_tf32(float f) {
    unsigned u;
    asm("cvt.rna.tf32.f32 %0, %1;" : "=r"(u) : "f"(f));
    return u;
}
__device__ __forceinline__ void store_cs2(float* p, float x, float y) {
    asm volatile("st.global.cs.v2.f32 [%0], {%1, %2};" :: "l"(p), "f"(x), "f"(y));
}

// ---------------- zeroing ----------------------------------------------------
__global__ void zero_col_k() {
    int i = blockIdx.x * blockDim.x + threadIdx.x;
    if (i < MCOLS) { g_colcnt[i] = 0; g_colcur[i] = 0; }
}
__global__ void zero_row_k() {
    int i = threadIdx.x;
    if (i < NROWS) { g_rowcnt[i] = 0; g_rowcur[i] = 0; }
}

// ---------------- W_all pre-format (once): tf32 fragment order --------------
__global__ void wprep_k(const float* __restrict__ W) {
    int i = blockIdx.x * 256 + threadIdx.x;   // grid 64 -> 16384 words
    if (i >= 16384) return;
    int w    = i & 3;
    int lane = (i >> 2) & 31;
    int j    = (i >> 7) & 3;
    int nwi  = (i >> 9) & 1;
    int ks   = i >> 10;
    int q = j * 4 + w;
    int t = lane & 3, g = lane >> 2;
    int k = ks * 8 + t + (q & 1) * 4;
    int n = nwi * 64 + (q >> 1) * 8 + g;
    g_Wfrag[i] = to_tf32(W[k * 128 + n]);
}

// ---------------- histograms -------------------------------------------------
__global__ void hist_col_k(const int* __restrict__ col_idx) {
    int e = blockIdx.x * blockDim.x + threadIdx.x;
    if (e < NNZ) atomicAdd(&g_colcnt[col_idx[e]], 1);
}
__global__ void hist_row_k(const int* __restrict__ row_idx) {  // grid 148
    __shared__ int h[NROWS];
    for (int i = threadIdx.x; i < NROWS; i += blockDim.x) h[i] = 0;
    __syncthreads();
    for (int e = blockIdx.x * blockDim.x + threadIdx.x; e < NNZ;
         e += gridDim.x * blockDim.x)
        atomicAdd(&h[row_idx[e]], 1);
    __syncthreads();
    for (int i = threadIdx.x; i < NROWS; i += blockDim.x) {
        int c = h[i];
        if (c) atomicAdd(&g_rowcnt[i], c);
    }
}

// ---------------- hierarchical column scan -----------------------------------
__global__ void scan1_k() {
    __shared__ int wsum[32];
    int i = blockIdx.x * 1024 + threadIdx.x;
    int lane = threadIdx.x & 31, wid = threadIdx.x >> 5;
    int v = (i < MCOLS) ? g_colcnt[i] : 0;
    #pragma unroll
    for (int off = 16; off > 0; off >>= 1) v += __shfl_down_sync(~0u, v, off);
    if (lane == 0) wsum[wid] = v;
    __syncthreads();
    if (wid == 0) {
        int s = wsum[lane];
        #pragma unroll
        for (int off = 16; off > 0; off >>= 1) s += __shfl_down_sync(~0u, s, off);
        if (lane == 0) g_partial[blockIdx.x] = s;
    }
}

__global__ void small_scan_k(const int* __restrict__ in, int* __restrict__ out, int n) {
    __shared__ int wsum[32];
    int tid = threadIdx.x, lane = tid & 31, wid = tid >> 5;
    int v = (tid < n) ? in[tid] : 0;
    int s = v;
    #pragma unroll
    for (int off = 1; off < 32; off <<= 1) {
        int t = __shfl_up_sync(~0u, s, off);
        if (lane >= off) s += t;
    }
    if (lane == 31) wsum[wid] = s;
    __syncthreads();
    if (wid == 0) {
        int ws = wsum[lane];
        #pragma unroll
        for (int off = 1; off < 32; off <<= 1) {
            int t = __shfl_up_sync(~0u, ws, off);
            if (lane >= off) ws += t;
        }
        wsum[lane] = ws;
    }
    __syncthreads();
    int excl = s - v + (wid > 0 ? wsum[wid - 1] : 0);
    if (tid < n) out[tid] = excl;
    if (tid == n - 1) out[n] = excl + v;
}

__global__ void scan3_k() {
    __shared__ int wsum[32];
    int i = blockIdx.x * 1024 + threadIdx.x;
    int lane = threadIdx.x & 31, wid = threadIdx.x >> 5;
    int v = (i < MCOLS) ? g_colcnt[i] : 0;
    int s = v;
    #pragma unroll
    for (int off = 1; off < 32; off <<= 1) {
        int t = __shfl_up_sync(~0u, s, off);
        if (lane >= off) s += t;
    }
    if (lane == 31) wsum[wid] = s;
    __syncthreads();
    if (wid == 0) {
        int ws = wsum[lane];
        #pragma unroll
        for (int off = 1; off < 32; off <<= 1) {
            int t = __shfl_up_sync(~0u, ws, off);
            if (lane >= off) ws += t;
        }
        wsum[lane] = ws;
    }
    __syncthreads();
    int excl = s - v + (wid > 0 ? wsum[wid - 1] : 0) + g_poff[blockIdx.x];
    if (i < MCOLS) g_coloff[i] = excl;
    if (i == MCOLS - 1) g_coloff[MCOLS] = excl + v;
}

// ---------------- scatters ---------------------------------------------------
__global__ void scatter_col_k(const int* __restrict__ col_idx) {
    int e = blockIdx.x * blockDim.x + threadIdx.x;
    if (e < NNZ) {
        int c = col_idx[e];
        int p = atomicAdd(&g_colcur[c], 1);
        g_colids[g_coloff[c] + p] = e;
    }
}
__global__ void scatter_row_k(const int* __restrict__ row_idx) {  // grid 148
    __shared__ int lcnt[NROWS];
    __shared__ int lbase[NROWS];
    const int tid = threadIdx.x;
    const int chunk = (NNZ + gridDim.x - 1) / gridDim.x;
    const int lo = blockIdx.x * chunk;
    const int hi = (lo + chunk < NNZ) ? lo + chunk : NNZ;

    for (int i = tid; i < NROWS; i += blockDim.x) lcnt[i] = 0;
    __syncthreads();
    for (int e = lo + tid; e < hi; e += blockDim.x)
        atomicAdd(&lcnt[row_idx[e]], 1);
    __syncthreads();
    for (int i = tid; i < NROWS; i += blockDim.x) {
        int c = lcnt[i];
        int b = c ? atomicAdd(&g_rowcur[i], c) : 0;
        lbase[i] = g_rowoff[i] + b;
        lcnt[i] = 0;
    }
    __syncthreads();
    for (int e = lo + tid; e < hi; e += blockDim.x) {
        int r = row_idx[e];
        int slot = atomicAdd(&lcnt[r], 1);
        g_rowids[lbase[r] + slot] = e;
    }
}

// ---------------- means ------------------------------------------------------
__global__ void colmean_k(const float* __restrict__ values) {
    int warp = (blockIdx.x * blockDim.x + threadIdx.x) >> 5;
    int lane = threadIdx.x & 31;
    if (warp >= MCOLS) return;
    int beg = g_coloff[warp], end = g_coloff[warp + 1];
    float4 acc = make_float4(0.f, 0.f, 0.f, 0.f);
    int j = beg;
    // unroll-8: two independent groups of 4 (MLP=8 on the value-row loads)
    for (; j + 8 <= end; j += 8) {
        int e0 = g_colids[j],     e1 = g_colids[j + 1];
        int e2 = g_colids[j + 2], e3 = g_colids[j + 3];
        int e4 = g_colids[j + 4], e5 = g_colids[j + 5];
        int e6 = g_colids[j + 6], e7 = g_colids[j + 7];
        float4 v0 = *(const float4*)(values + (size_t)e0 * D + lane * 4);
        float4 v1 = *(const float4*)(values + (size_t)e1 * D + lane * 4);
        float4 v2 = *(const float4*)(values + (size_t)e2 * D + lane * 4);
        float4 v3 = *(const float4*)(values + (size_t)e3 * D + lane * 4);
        float4 v4 = *(const float4*)(values + (size_t)e4 * D + lane * 4);
        float4 v5 = *(const float4*)(values + (size_t)e5 * D + lane * 4);
        float4 v6 = *(const float4*)(values + (size_t)e6 * D + lane * 4);
        float4 v7 = *(const float4*)(values + (size_t)e7 * D + lane * 4);
        acc.x += (v0.x + v1.x) + (v2.x + v3.x);
        acc.y += (v0.y + v1.y) + (v2.y + v3.y);
        acc.z += (v0.z + v1.z) + (v2.z + v3.z);
        acc.w += (v0.w + v1.w) + (v2.w + v3.w);
        acc.x += (v4.x + v5.x) + (v6.x + v7.x);
        acc.y += (v4.y + v5.y) + (v6.y + v7.y);
        acc.z += (v4.z + v5.z) + (v6.z + v7.z);
        acc.w += (v4.w + v5.w) + (v6.w + v7.w);
    }
    for (; j + 4 <= end; j += 4) {
        int e0 = g_colids[j], e1 = g_colids[j + 1];
        int e2 = g_colids[j + 2], e3 = g_colids[j + 3];
        float4 v0 = *(const float4*)(values + (size_t)e0 * D + lane * 4);
        float4 v1 = *(const float4*)(values + (size_t)e1 * D + lane * 4);
        float4 v2 = *(const float4*)(values + (size_t)e2 * D + lane * 4);
        float4 v3 = *(const float4*)(values + (size_t)e3 * D + lane * 4);
        acc.x += (v0.x + v1.x) + (v2.x + v3.x);
        acc.y += (v0.y + v1.y) + (v2.y + v3.y);
        acc.z += (v0.z + v1.z) + (v2.z + v3.z);
        acc.w += (v0.w + v1.w) + (v2.w + v3.w);
    }
    for (; j < end; j++) {
        int e = g_colids[j];
        float4 v = *(const float4*)(values + (size_t)e * D + lane * 4);
        acc.x += v.x; acc.y += v.y; acc.z += v.z; acc.w += v.w;
    }
    int n = end - beg;
    float inv = 1.0f / (float)(n > 1 ? n : 1);
    acc.x *= inv; acc.y *= inv; acc.z *= inv; acc.w *= inv;
    *(float4*)(g_colmean + (size_t)warp * D + lane * 4) = acc;
}

__global__ void rowmean_k(const float* __restrict__ values) {
    int r = blockIdx.x;
    int lane = threadIdx.x & 31, w = threadIdx.x >> 5;  // 8 warps
    int beg = g_rowoff[r], end = g_rowoff[r + 1];
    float4 acc = make_float4(0.f, 0.f, 0.f, 0.f);
    for (int j = beg + w; j < end; j += 8) {
        int e = g_rowids[j];
        float4 v = *(const float4*)(values + (size_t)e * D + lane * 4);
        acc.x += v.x; acc.y += v.y; acc.z += v.z; acc.w += v.w;
    }
    __shared__ float4 s[8][32];
    s[w][lane] = acc;
    __syncthreads();
    if (w == 0) {
        #pragma unroll
        for (int k = 1; k < 8; k++) {
            float4 t = s[k][lane];
            acc.x += t.x; acc.y += t.y; acc.z += t.z; acc.w += t.w;
        }
        *(float4*)(g_rowsum + (size_t)r * D + lane * 4) = acc;
        int n = end - beg;
        float inv = 1.0f / (float)(n > 1 ? n : 1);
        acc.x *= inv; acc.y *= inv; acc.z *= inv; acc.w *= inv;
        *(float4*)(g_rowmean + (size_t)r * D + lane * 4) = acc;
    }
}

// ---------------- global-mean + fused constant -------------------------------
__global__ void cconst_k(const float* __restrict__ W_both,
                         const float* __restrict__ b_all, const float* __restrict__ b_n,
                         const float* __restrict__ b_m,  const float* __restrict__ b_both) {
    __shared__ float gm[D];
    int t = threadIdx.x;
    float s = 0.f;
    for (int r = 0; r < NROWS; r++) s += g_rowsum[r * D + t];
    gm[t] = s * (1.0f / (float)NNZ);
    __syncthreads();
    float acc = 0.f;
    for (int k = 0; k < D; k++) acc += gm[k] * W_both[k * D + t];
    g_C[t] = 0.25f * (acc + b_all[t] + b_n[t] + b_m[t] + b_both[t]);
}

// ---------------- mma.sync tf32 primitive ------------------------------------
__device__ __forceinline__ void mma_tf32(float* c, const unsigned* a, unsigned b0, unsigned b1) {
    asm volatile(
        "mma.sync.aligned.m16n8k8.row.col.f32.tf32.tf32.f32 "
        "{%0,%1,%2,%3}, {%4,%5,%6,%7}, {%8,%9}, {%0,%1,%2,%3};"
        : "+f"(c[0]), "+f"(c[1]), "+f"(c[2]), "+f"(c[3])
        : "r"(a[0]), "r"(a[1]), "r"(a[2]), "r"(a[3]), "r"(b0), "r"(b1));
}

// ======== small GEMMs (G, H): out = 0.25*(A@W)  (validated path) =============
#define AS_STRIDE 68
#define WS_STRIDE 132
#define SMEM_AS   0
#define SMEM_WS   (128 * AS_STRIDE * 4)
#define SMEM_TOT  (SMEM_WS + 64 * WS_STRIDE * 4)

__global__ void __launch_bounds__(256, 2)
gemm_tc(const float* __restrict__ A, const float* __restrict__ W,
        float* __restrict__ out, int M) {
    extern __shared__ char smem[];
    float* As = (float*)(smem + SMEM_AS);
    float* Ws = (float*)(smem + SMEM_WS);

    const int tid  = threadIdx.x;
    const int lane = tid & 31;
    const int wid  = tid >> 5;
    const int g    = lane >> 2;
    const int t    = lane & 3;
    const int mw   = (wid & 3) * 32;
    const int nw   = (wid >> 2) * 64;
    const int m_base = blockIdx.x * 128;

    float acc[2][8][4];
    #pragma unroll
    for (int f = 0; f < 2; f++)
        #pragma unroll
        for (int nf = 0; nf < 8; nf++)
            #pragma unroll
            for (int i = 0; i < 4; i++) acc[f][nf][i] = 0.f;

    for (int kc = 0; kc < 128; kc += 64) {
        #pragma unroll
        for (int it = 0; it < 8; it++) {
            int i = it * 256 + tid;
            int m = i >> 4, kq = i & 15;
            int row = m_base + m;
            if (row >= M) row = M - 1;
            float4 v = *(const float4*)(A + (size_t)row * 128 + kc + kq * 4);
            unsigned* dst = (unsigned*)(As + m * AS_STRIDE + kq * 4);
            dst[0] = to_tf32(v.x); dst[1] = to_tf32(v.y);
            dst[2] = to_tf32(v.z); dst[3] = to_tf32(v.w);
        }
        #pragma unroll
        for (int it = 0; it < 8; it++) {
            int i = it * 256 + tid;
            int k = i >> 5, nq = i & 31;
            float4 v = *(const float4*)(W + (size_t)(kc + k) * 128 + nq * 4);
            unsigned* dst = (unsigned*)(Ws + k * WS_STRIDE + nq * 4);
            dst[0] = to_tf32(v.x); dst[1] = to_tf32(v.y);
            dst[2] = to_tf32(v.z); dst[3] = to_tf32(v.w);
        }
        __syncthreads();

        #pragma unroll
        for (int ks = 0; ks < 8; ks++) {
            int k0 = ks * 8;
            unsigned a[2][4];
            #pragma unroll
            for (int f = 0; f < 2; f++) {
                const unsigned* ap = (const unsigned*)(As + (mw + f * 16 + g) * AS_STRIDE + k0 + t);
                const unsigned* ap8 = ap + 8 * AS_STRIDE;
                a[f][0] = ap[0];  a[f][1] = ap8[0];
                a[f][2] = ap[4];  a[f][3] = ap8[4];
            }
            #pragma unroll
            for (int nf = 0; nf < 8; nf++) {
                int n = nw + nf * 8 + g;
                unsigned b0 = *(const unsigned*)(Ws + (k0 + t) * WS_STRIDE + n);
                unsigned b1 = *(const unsigned*)(Ws + (k0 + t + 4) * WS_STRIDE + n);
                mma_tf32(acc[0][nf], a[0], b0, b1);
                mma_tf32(acc[1][nf], a[1], b0, b1);
            }
        }
        __syncthreads();
    }

    #pragma unroll
    for (int f = 0; f < 2; f++) {
        #pragma unroll
        for (int nf = 0; nf < 8; nf++) {
            int nb = nw + nf * 8 + 2 * t;
            #pragma unroll
            for (int half = 0; half < 2; half++) {
                int m_loc = mw + f * 16 + g + half * 8;
                int e = m_base + m_loc;
                if (e >= M) continue;
                float2 o;
                o.x = acc[f][nf][half * 2 + 0] * 0.25f;
                o.y = acc[f][nf][half * 2 + 1] * 0.25f;
                *(float2*)(out + (size_t)e * 128 + nb) = o;
            }
        }
    }
}

// ======== main GEMM: fragment-ordered A AND B, fused epilogue (R13) ==========
// out = 0.25*(A@W_all) + G[col] + H[row] + C
// AsF chunk: [ks(8)][mwi(4)][f(2)][lanepos^ks (32)][w(4)]; 32 KB
// Wf  chunk: [ks(8)][nwi(2)][j(4)][lane(32)][w(4)]; 32 KB
#define MS_ASF  0                              // 32768
#define MS_WF   32768                          // 32768
#define MS_SC   65536
#define MS_IC   66048
#define MS_IR   66560
#define MS_TOT  67072

__global__ void __launch_bounds__(256, 2)
gemm_tcm(const float* __restrict__ A, float* __restrict__ out, int M,
         const int* __restrict__ colidx, const int* __restrict__ rowidx) {
    extern __shared__ char smem[];
    unsigned* AsF = (unsigned*)(smem + MS_ASF);
    uint4*    Wf  = (uint4*)(smem + MS_WF);
    float* sC = (float*)(smem + MS_SC);
    int*   sc = (int*)  (smem + MS_IC);
    int*   sr = (int*)  (smem + MS_IR);

    const int tid  = threadIdx.x;
    const int lane = tid & 31;
    const int wid  = tid >> 5;
    const int g    = lane >> 2;
    const int t    = lane & 3;
    const int mw   = (wid & 3) * 32;
    const int mwi  = (wid & 3);
    const int nw   = (wid >> 2) * 64;
    const int nwi  = (wid >> 2);
    const int m_base = blockIdx.x * 128;

    if (tid < 128) {
        int e = m_base + tid;
        if (e >= M) e = M - 1;
        sc[tid] = colidx[e];
        sr[tid] = rowidx[e];
        sC[tid] = g_C[tid];
    }

    float acc[2][8][4];
    #pragma unroll
    for (int f = 0; f < 2; f++)
        #pragma unroll
        for (int nf = 0; nf < 8; nf++)
            #pragma unroll
            for (int i = 0; i < 4; i++) acc[f][nf][i] = 0.f;

    for (int kc = 0; kc < 128; kc += 64) {
        // A chunk -> fragment-ordered smem (cvt at store, ks-XOR swizzle)
        #pragma unroll
        for (int it = 0; it < 8; it++) {
            int i = it * 256 + tid;
            int m = i >> 4, kq = i & 15;
            int row = m_base + m;
            if (row >= M) row = M - 1;
            float4 v = *(const float4*)(A + (size_t)row * 128 + kc + kq * 4);
            int ks = kq >> 1, half = kq & 1;
            int fm = (m >> 4) & 1, r8 = (m >> 3) & 1, gg = m & 7;
            unsigned* basep = AsF + ks * 1024 + (m >> 5) * 256 + fm * 128 + half * 2 + r8;
            basep[(((gg * 4 + 0) ^ ks)) << 2] = to_tf32(v.x);
            basep[(((gg * 4 + 1) ^ ks)) << 2] = to_tf32(v.y);
            basep[(((gg * 4 + 2) ^ ks)) << 2] = to_tf32(v.z);
            basep[(((gg * 4 + 3) ^ ks)) << 2] = to_tf32(v.w);
        }
        // W fragment chunk: contiguous copy (1024 words per ks-step)
        {
            const uint4* src = (const uint4*)(g_Wfrag + (kc >> 3) * 1024);
            #pragma unroll
            for (int it = 0; it < 8; it++) Wf[it * 256 + tid] = src[it * 256 + tid];
        }
        __syncthreads();

        #pragma unroll
        for (int ks = 0; ks < 8; ks++) {
            // A fragments: 2 conflict-free LDS.128 (swizzled lane)
            const uint4* ap = (const uint4*)AsF + (size_t)(ks * 256 + mwi * 64) + (lane ^ ks);
            uint4 qa0 = ap[0];       // f = 0
            uint4 qa1 = ap[32];      // f = 1
            unsigned a0[4] = {qa0.x, qa0.y, qa0.z, qa0.w};
            unsigned a1[4] = {qa1.x, qa1.y, qa1.z, qa1.w};
            // B fragments: 4 conflict-free LDS.128 -> breg[16]
            unsigned breg[16];
            {
                const uint4* bp = Wf + (size_t)((ks * 2 + nwi) * 4) * 32 + lane;
                uint4 q0 = bp[0];
                uint4 q1 = bp[32];
                uint4 q2 = bp[64];
                uint4 q3 = bp[96];
                breg[0]=q0.x; breg[1]=q0.y; breg[2]=q0.z; breg[3]=q0.w;
                breg[4]=q1.x; breg[5]=q1.y; breg[6]=q1.z; breg[7]=q1.w;
                breg[8]=q2.x; breg[9]=q2.y; breg[10]=q2.z; breg[11]=q2.w;
                breg[12]=q3.x; breg[13]=q3.y; breg[14]=q3.z; breg[15]=q3.w;
            }
            #pragma unroll
            for (int nf = 0; nf < 8; nf++) {
                mma_tf32(acc[0][nf], a0, breg[2 * nf], breg[2 * nf + 1]);
                mma_tf32(acc[1][nf], a1, breg[2 * nf], breg[2 * nf + 1]);
            }
        }
        __syncthreads();
    }

    #pragma unroll
    for (int f = 0; f < 2; f++) {
        #pragma unroll
        for (int nf = 0; nf < 8; nf++) {
            int nb = nw + nf * 8 + 2 * t;
            #pragma unroll
            for (int half = 0; half < 2; half++) {
                int m_loc = mw + f * 16 + g + half * 8;
                int e = m_base + m_loc;
                if (e >= M) continue;
                float ox = acc[f][nf][half * 2 + 0] * 0.25f;
                float oy = acc[f][nf][half * 2 + 1] * 0.25f;
                int c = sc[m_loc], r = sr[m_loc];
                float2 gv = *(const float2*)(g_G + (size_t)c * 128 + nb);
                float2 hv = *(const float2*)(g_H + (size_t)r * 128 + nb);
                ox += gv.x + hv.x + sC[nb];
                oy += gv.y + hv.y + sC[nb + 1];
                // streaming store: out is write-once; keep G/H resident in L2
                store_cs2(out + (size_t)e * 128 + nb, ox, oy);
            }
        }
    }
}

// ---------------------------------------------------------------------------
extern "C" void kernel_launch(void* const* d_in, const int* in_sizes, int n_in,
                              void* d_out, int out_size) {
    const float* values  = (const float*)d_in[0];
    const int*   row_idx = (const int*)  d_in[1];
    const int*   col_idx = (const int*)  d_in[2];
    const float* W_all   = (const float*)d_in[3];
    const float* b_all   = (const float*)d_in[4];
    const float* W_n     = (const float*)d_in[5];
    const float* b_n     = (const float*)d_in[6];
    const float* W_m     = (const float*)d_in[7];
    const float* b_m     = (const float*)d_in[8];
    const float* W_both  = (const float*)d_in[9];
    const float* b_both  = (const float*)d_in[10];
    float* out = (float*)d_out;

    static cudaStream_t s_col = nullptr, s_row = nullptr;
    static cudaEvent_t ev_fork = nullptr, ev_jc = nullptr, ev_jr = nullptr;
    if (!s_col) {
        cudaStreamCreateWithFlags(&s_col, cudaStreamNonBlocking);
        cudaStreamCreateWithFlags(&s_row, cudaStreamNonBlocking);
        cudaEventCreateWithFlags(&ev_fork, cudaEventDisableTiming);
        cudaEventCreateWithFlags(&ev_jc, cudaEventDisableTiming);
        cudaEventCreateWithFlags(&ev_jr, cudaEventDisableTiming);
        cudaFuncSetAttribute(gemm_tc,  cudaFuncAttributeMaxDynamicSharedMemorySize, SMEM_TOT);
        cudaFuncSetAttribute(gemm_tcm, cudaFuncAttributeMaxDynamicSharedMemorySize, MS_TOT);
    }

    float* colmean_p; cudaGetSymbolAddress((void**)&colmean_p, g_colmean);
    float* rowmean_p; cudaGetSymbolAddress((void**)&rowmean_p, g_rowmean);
    float* G_p;       cudaGetSymbolAddress((void**)&G_p, g_G);
    float* H_p;       cudaGetSymbolAddress((void**)&H_p, g_H);
    int* partial_p;   cudaGetSymbolAddress((void**)&partial_p, g_partial);
    int* poff_p;      cudaGetSymbolAddress((void**)&poff_p, g_poff);
    int* rowcnt_p;    cudaGetSymbolAddress((void**)&rowcnt_p, g_rowcnt);
    int* rowoff_p;    cudaGetSymbolAddress((void**)&rowoff_p, g_rowoff);

    cudaEventRecord(ev_fork, 0);
    cudaStreamWaitEvent(s_col, ev_fork, 0);
    cudaStreamWaitEvent(s_row, ev_fork, 0);

    // ---- col chain (s_col) ----
    wprep_k<<<64, 256, 0, s_col>>>(W_all);
    zero_col_k<<<(MCOLS + 255) / 256, 256, 0, s_col>>>();
    hist_col_k<<<(NNZ + 255) / 256, 256, 0, s_col>>>(col_idx);
    scan1_k<<<SCAN_BLOCKS, 1024, 0, s_col>>>();
    small_scan_k<<<1, 1024, 0, s_col>>>(partial_p, poff_p, SCAN_BLOCKS);
    scan3_k<<<SCAN_BLOCKS, 1024, 0, s_col>>>();
    scatter_col_k<<<(NNZ + 255) / 256, 256, 0, s_col>>>(col_idx);
    colmean_k<<<(MCOLS * 32 + 255) / 256, 256, 0, s_col>>>(values);
    gemm_tc<<<(MCOLS + 127) / 128, 256, SMEM_TOT, s_col>>>(colmean_p, W_n, G_p, MCOLS);

    // ---- row chain (s_row) ----
    zero_row_k<<<1, 512, 0, s_row>>>();
    hist_row_k<<<148, 256, 0, s_row>>>(row_idx);
    small_scan_k<<<1, 1024, 0, s_row>>>(rowcnt_p, rowoff_p, NROWS);
    scatter_row_k<<<148, 256, 0, s_row>>>(row_idx);
    rowmean_k<<<NROWS, 256, 0, s_row>>>(values);
    cconst_k<<<1, 128, 0, s_row>>>(W_both, b_all, b_n, b_m, b_both);
    gemm_tc<<<(NROWS + 127) / 128, 256, SMEM_TOT, s_row>>>(rowmean_p, W_m, H_p, NROWS);

    // join, then main GEMM (fused epilogue)
    cudaEventRecord(ev_jc, s_col);
    cudaEventRecord(ev_jr, s_row);
    cudaStreamWaitEvent(0, ev_jc, 0);
    cudaStreamWaitEvent(0, ev_jr, 0);
    gemm_tcm<<<(NNZ + 127) / 128, 256, MS_TOT>>>(values, out, NNZ, col_idx, row_idx);
}